// round 4
// baseline (speedup 1.0000x reference)
#include <cuda_runtime.h>
#include <cstdint>

#define NOPS  102400
#define NDAG  1024
#define OPD   100
#define EDIM  256
#define H1D   32
#define H2D   16
#define NWRK  64
#define MTILE 256
#define NBLK  (NOPS / MTILE)      // 400

// ---------------- device scratch (no allocations allowed) ----------------
__device__ float  g_Aop[NDAG * H1D];
__device__ float  g_Apr[NDAG * H1D];
__device__ float  g_bmax[NBLK];
__device__ float  g_bsum[NBLK];
__device__ float4 g_Bfrag[4096];   // [32 kstep][4 nbl][32 lane] = {b0hi,b1hi,b0lo,b1lo}

// ---------------- smem layout (bytes) ----------------
#define B_OFF   0                  // 65536: B fragments hi/lo
#define A_OFF   65536              // 2 x 65536: A fragment double buffer
#define ABUF    65536
#define W2_OFF  196608             // 512 floats
#define B2_OFF  (W2_OFF + 2048)
#define W3_OFF  (B2_OFF + 64)
#define RED_OFF (W3_OFF + 64)
#define SMEM_BYTES (RED_OFF + 64)  // 198848

// ---------------- helpers ----------------
__device__ __forceinline__ void cp16(uint32_t dst, const void* src) {
    asm volatile("cp.async.cg.shared.global [%0], [%1], 16;" :: "r"(dst), "l"(src));
}
__device__ __forceinline__ void mma_tf32(float* c, const uint32_t* a,
                                         uint32_t b0, uint32_t b1) {
    asm volatile(
        "mma.sync.aligned.m16n8k8.row.col.f32.tf32.tf32.f32 "
        "{%0,%1,%2,%3},{%4,%5,%6,%7},{%8,%9},{%0,%1,%2,%3};"
        : "+f"(c[0]), "+f"(c[1]), "+f"(c[2]), "+f"(c[3])
        : "r"(a[0]), "r"(a[1]), "r"(a[2]), "r"(a[3]), "r"(b0), "r"(b1));
}
__device__ __forceinline__ void split32(float v, uint32_t& hi, uint32_t& lo) {
    uint32_t u = __float_as_uint(v);
    hi = u & 0xFFFFE000u;
    lo = __float_as_uint(v - __uint_as_float(hi));
}

// ---------------------------------------------------------------------------
// precompute: blocks [0,256): per-dag layer-1 partials for both heads
//             blocks [256,272): B fragments (W1 x-part, hi/lo, mma layout)
// ---------------------------------------------------------------------------
__global__ __launch_bounds__(128) void precompute_kernel(
    const float* __restrict__ y, const float* __restrict__ z,
    const float* __restrict__ opW1, const float* __restrict__ opb1,
    const float* __restrict__ prW1, const float* __restrict__ prb1)
{
    if (blockIdx.x >= 256) {
        // B fragment prep: 4096 float4 entries over 16 blocks x 128 threads x 2
        int t = (blockIdx.x - 256) * 128 + threadIdx.x;
        #pragma unroll
        for (int q = 0; q < 2; q++) {
            int e = t * 2 + q;                 // 0..4095
            int lane = e & 31;
            int nbl  = (e >> 5) & 3;
            int kst  = e >> 7;                 // 0..31
            int k0 = kst * 8 + (lane & 3);
            int n  = nbl * 8 + (lane >> 2);
            float b0 = __ldg(opW1 + k0 * H1D + n);
            float b1 = __ldg(opW1 + (k0 + 4) * H1D + n);
            uint32_t h0, l0, h1, l1;
            split32(b0, h0, l0);
            split32(b1, h1, l1);
            float4 v;
            v.x = __uint_as_float(h0); v.y = __uint_as_float(h1);
            v.z = __uint_as_float(l0); v.w = __uint_as_float(l1);
            g_Bfrag[e] = v;
        }
        return;
    }
    int warp = threadIdx.x >> 5;
    int lane = threadIdx.x & 31;
    int d = blockIdx.x * 4 + warp;
    const float* yd = y + d * EDIM;
    float aop = opb1[lane];
    float apr = prb1[lane];
    #pragma unroll 4
    for (int k = 0; k < EDIM; k++) {
        float yv = __ldg(yd + k);
        float zv = __ldg(z + k);
        aop = fmaf(yv, __ldg(opW1 + (EDIM + k) * H1D + lane), aop);
        aop = fmaf(zv, __ldg(opW1 + (2 * EDIM + k) * H1D + lane), aop);
        apr = fmaf(yv, __ldg(prW1 + (1 + k) * H1D + lane), apr);
        apr = fmaf(zv, __ldg(prW1 + (1 + EDIM + k) * H1D + lane), apr);
    }
    g_Aop[d * H1D + lane] = aop;
    g_Apr[d * H1D + lane] = apr;
}

// ---------------------------------------------------------------------------
// op main: [256 x 256] x [256 x 32] via 3xTF32 mma.sync + fused epilogue.
// 8 warps: warp w covers rows 32w..32w+31 (2 m-blocks), full N=32 (4 n-blocks).
// A fragment smem layout per (wm=row/16, kk): 4 slots x 32 lanes, 512B,
//   lane slot addr = s*32 + ((g ^ ((kk*2 + (s>>1)) & 7)) * 4 + c), g=lane/4,c=lane%4
// ---------------------------------------------------------------------------
__global__ __launch_bounds__(256, 1) void op_main_kernel(
    const float* __restrict__ x,
    const float* __restrict__ opW2, const float* __restrict__ opb2,
    const float* __restrict__ opW3, const float* __restrict__ opb3,
    const float* __restrict__ opmsk,
    float* __restrict__ out)
{
    extern __shared__ char sm[];
    float* s_B   = (float*)(sm + B_OFF);
    float* s_w2  = (float*)(sm + W2_OFF);
    float* s_b2  = (float*)(sm + B2_OFF);
    float* s_w3  = (float*)(sm + W3_OFF);
    float* s_red = (float*)(sm + RED_OFF);

    const int tid  = threadIdx.x;
    const int warp = tid >> 5;
    const int lane = tid & 31;
    const int g    = lane >> 2;
    const int cc   = lane & 3;
    const int blk  = blockIdx.x;

    // group0: B fragments (64KB, shared data -> L2 hits after first CTAs)
    {
        uint32_t db = (uint32_t)__cvta_generic_to_shared(sm + B_OFF);
        #pragma unroll
        for (int i = 0; i < 16; i++) {
            int idx = i * 256 + tid;
            cp16(db + idx * 16, g_Bfrag + idx);
        }
        asm volatile("cp.async.commit_group;");
    }

    // A staging: chunk c (64 k-values) -> fragment layout, one commit group
    const float4* xs = (const float4*)x + (size_t)(blk * MTILE) * (EDIM / 4);
    auto stageA = [&](int c, int buf) {
        uint32_t ab = (uint32_t)__cvta_generic_to_shared(sm + A_OFF + buf * ABUF);
        #pragma unroll
        for (int i = 0; i < 16; i++) {
            int lin = i * 256 + tid;
            int row = lin >> 4, j = lin & 15;        // j = float4 col in chunk
            int kk = j >> 1, h = j & 1;
            int r16 = row & 15, wm = row >> 4;
            int rg = r16 & 7, p = r16 >> 3;
            int s = h * 2 + p;
            int sg = rg ^ ((kk * 2 + h) & 7);
            uint32_t dstf = (uint32_t)((wm * 8 + kk) * 128 + s * 32 + sg * 4);
            cp16(ab + dstf * 4, xs + row * 64 + c * 16 + j);
        }
        asm volatile("cp.async.commit_group;");
    };

    stageA(0, 0);
    stageA(1, 1);

    for (int i = tid; i < H1D * H2D; i += 256) s_w2[i] = opW2[i];
    if (tid < H2D) { s_b2[tid] = opb2[tid]; s_w3[tid] = opW3[tid]; }

    float acc[2][4][4];
    #pragma unroll
    for (int m = 0; m < 2; m++)
        #pragma unroll
        for (int nb = 0; nb < 4; nb++)
            #pragma unroll
            for (int r = 0; r < 4; r++) acc[m][nb][r] = 0.f;

    for (int c = 0; c < 4; c++) {
        if (c < 3) asm volatile("cp.async.wait_group 1;");
        else       asm volatile("cp.async.wait_group 0;");
        __syncthreads();

        const float* ab = (const float*)(sm + A_OFF + (c & 1) * ABUF);
        #pragma unroll
        for (int kk = 0; kk < 8; kk++) {
            const int kstg = c * 8 + kk;
            // B fragments: 4 n-blocks, LDS.128 each {b0hi,b1hi,b0lo,b1lo}
            float4 Bf[4];
            #pragma unroll
            for (int nb = 0; nb < 4; nb++)
                Bf[nb] = *(const float4*)(s_B + ((kstg * 4 + nb) * 32 + lane) * 4);
            // A fragments: 2 m-blocks x 4 slots, split hi/lo in registers
            uint32_t Ah[2][4], Al[2][4];
            #pragma unroll
            for (int m = 0; m < 2; m++) {
                #pragma unroll
                for (int s = 0; s < 4; s++) {
                    int sg = g ^ ((kk * 2 + (s >> 1)) & 7);
                    float v = ab[((warp * 2 + m) * 8 + kk) * 128 + s * 32 + sg * 4 + cc];
                    split32(v, Ah[m][s], Al[m][s]);
                }
            }
            #pragma unroll
            for (int m = 0; m < 2; m++) {
                #pragma unroll
                for (int nb = 0; nb < 4; nb++) {
                    uint32_t bh0 = __float_as_uint(Bf[nb].x);
                    uint32_t bh1 = __float_as_uint(Bf[nb].y);
                    uint32_t bl0 = __float_as_uint(Bf[nb].z);
                    uint32_t bl1 = __float_as_uint(Bf[nb].w);
                    mma_tf32(acc[m][nb], Ah[m], bh0, bh1);
                    mma_tf32(acc[m][nb], Ah[m], bl0, bl1);
                    mma_tf32(acc[m][nb], Al[m], bh0, bh1);
                }
            }
        }
        __syncthreads();
        if (c < 2) stageA(c + 2, c & 1);
    }

    // ---- scatter C into s_h [256 rows x stride 33] (reuse A buffer 0) ----
    float* s_h = (float*)(sm + A_OFF);
    #pragma unroll
    for (int m = 0; m < 2; m++) {
        int row = warp * 32 + m * 16 + g;
        #pragma unroll
        for (int nb = 0; nb < 4; nb++) {
            int col = nb * 8 + 2 * cc;
            s_h[row * 33 + col]           = acc[m][nb][0];
            s_h[row * 33 + col + 1]       = acc[m][nb][1];
            s_h[(row + 8) * 33 + col]     = acc[m][nb][2];
            s_h[(row + 8) * 33 + col + 1] = acc[m][nb][3];
        }
    }
    __syncthreads();

    // ---- layers 2/3 + mask: one op per thread ----
    const int gop = blk * MTILE + tid;
    const int dag = gop / OPD;
    const float* A = g_Aop + dag * H1D;
    float h2[H2D];
    #pragma unroll
    for (int j = 0; j < H2D; j++) h2[j] = s_b2[j];
    const float* hrow = s_h + tid * 33;
    #pragma unroll
    for (int k = 0; k < H1D; k++) {
        float hv = fmaxf(hrow[k] + __ldg(A + k), 0.f);
        #pragma unroll
        for (int j = 0; j < H2D; j++) h2[j] = fmaf(hv, s_w2[k * H2D + j], h2[j]);
    }
    float l = __ldg(opb3);
    #pragma unroll
    for (int j = 0; j < H2D; j++) l = fmaf(fmaxf(h2[j], 0.f), s_w3[j], l);
    l -= (1.f - __ldg(opmsk + gop)) * 1000.f;
    out[gop] = l;

    // ---- per-block online softmax partials over 256 logits ----
    float mx = l;
    #pragma unroll
    for (int off = 16; off; off >>= 1)
        mx = fmaxf(mx, __shfl_xor_sync(0xffffffffu, mx, off));
    if (lane == 0) s_red[warp] = mx;
    __syncthreads();
    float bm = s_red[0];
    #pragma unroll
    for (int i = 1; i < 8; i++) bm = fmaxf(bm, s_red[i]);
    float e = __expf(l - bm);
    #pragma unroll
    for (int off = 16; off; off >>= 1)
        e += __shfl_xor_sync(0xffffffffu, e, off);
    if (lane == 0) s_red[8 + warp] = e;
    __syncthreads();
    if (tid == 0) {
        float s = 0.f;
        #pragma unroll
        for (int i = 0; i < 8; i++) s += s_red[8 + i];
        g_bmax[blk] = bm;
        g_bsum[blk] = s;
    }
}

// ---------------------------------------------------------------------------
// finalize: every block redundantly reduces the 400 partials + normalizes
// ---------------------------------------------------------------------------
__global__ __launch_bounds__(256) void finalize_kernel(float* __restrict__ out)
{
    __shared__ float sr[16];
    __shared__ float sM, sS;
    const int tid = threadIdx.x;
    const int wid = tid >> 5, lane = tid & 31;

    float bm0 = g_bmax[tid];
    float bm1 = (tid + 256 < NBLK) ? g_bmax[tid + 256] : -1e30f;
    float m = fmaxf(bm0, bm1);
    #pragma unroll
    for (int off = 16; off; off >>= 1)
        m = fmaxf(m, __shfl_xor_sync(0xffffffffu, m, off));
    if (lane == 0) sr[wid] = m;
    __syncthreads();
    if (tid == 0) {
        float M = sr[0];
        #pragma unroll
        for (int i = 1; i < 8; i++) M = fmaxf(M, sr[i]);
        sM = M;
    }
    __syncthreads();
    const float M = sM;
    float s = g_bsum[tid] * __expf(bm0 - M);
    if (tid + 256 < NBLK) s += g_bsum[tid + 256] * __expf(bm1 - M);
    #pragma unroll
    for (int off = 16; off; off >>= 1)
        s += __shfl_xor_sync(0xffffffffu, s, off);
    if (lane == 0) sr[8 + wid] = s;
    __syncthreads();
    if (tid == 0) {
        float S = 0.f;
        #pragma unroll
        for (int i = 0; i < 8; i++) S += sr[8 + i];
        sS = S;
    }
    __syncthreads();
    const float inv = 1.f / sS;
    const int i = blockIdx.x * 256 + tid;
    out[i] = __expf(out[i] - M) * inv;
}

// ---------------------------------------------------------------------------
// prlvl: 256-thread blocks, 4 dags/block, 64 workers per dag (2 warps)
// ---------------------------------------------------------------------------
__global__ __launch_bounds__(256) void prlvl_kernel(
    const float* __restrict__ prW1,
    const float* __restrict__ prW2, const float* __restrict__ prb2,
    const float* __restrict__ prW3, const float* __restrict__ prb3,
    const float* __restrict__ prmsk,
    float* __restrict__ out)
{
    __shared__ float sA[4 * H1D], sr0[H1D], sw2[H1D * H2D], sb2[H2D], sw3[H2D];
    __shared__ float sp[8], sp2[8];
    const int tid = threadIdx.x;
    const int sub = tid >> 6;
    const int w = tid & 63;
    const int d = blockIdx.x * 4 + sub;

    if (tid < 128) sA[tid] = g_Apr[blockIdx.x * 128 + tid];
    if (tid < H1D) sr0[tid] = prW1[tid];
    for (int i = tid; i < H1D * H2D; i += 256) sw2[i] = prW2[i];
    if (tid < H2D) { sb2[tid] = prb2[tid]; sw3[tid] = prW3[tid]; }
    __syncthreads();

    const float limit = (float)(w + 1);
    const float* A = sA + sub * H1D;
    float h2[H2D];
    #pragma unroll
    for (int j = 0; j < H2D; j++) h2[j] = sb2[j];
    #pragma unroll
    for (int k = 0; k < H1D; k++) {
        float hv = fmaxf(fmaf(limit, sr0[k], A[k]), 0.f);
        #pragma unroll
        for (int j = 0; j < H2D; j++) h2[j] = fmaf(hv, sw2[k * H2D + j], h2[j]);
    }
    float l = __ldg(prb3);
    #pragma unroll
    for (int j = 0; j < H2D; j++) l = fmaf(fmaxf(h2[j], 0.f), sw3[j], l);
    l -= (1.f - __ldg(prmsk + d * NWRK + w)) * 1000.f;

    float m = l;
    #pragma unroll
    for (int off = 16; off; off >>= 1)
        m = fmaxf(m, __shfl_xor_sync(0xffffffffu, m, off));
    if ((tid & 31) == 0) sp[tid >> 5] = m;
    __syncthreads();
    float bm = fmaxf(sp[2 * sub], sp[2 * sub + 1]);
    float eo = __expf(l - bm);
    float e = eo;
    #pragma unroll
    for (int off = 16; off; off >>= 1)
        e += __shfl_xor_sync(0xffffffffu, e, off);
    if ((tid & 31) == 0) sp2[tid >> 5] = e;
    __syncthreads();
    float s = sp2[2 * sub] + sp2[2 * sub + 1];
    out[NOPS + d * NWRK + w] = eo / s;
}

// ---------------------------------------------------------------------------
// Launch
// ---------------------------------------------------------------------------
extern "C" void kernel_launch(void* const* d_in, const int* in_sizes, int n_in,
                              void* d_out, int out_size)
{
    const int xi = n_in - 17;
    const float* x     = (const float*)d_in[xi + 0];
    const float* y     = (const float*)d_in[xi + 1];
    const float* z     = (const float*)d_in[xi + 2];
    const float* opmsk = (const float*)d_in[xi + 3];
    const float* prmsk = (const float*)d_in[xi + 4];
    const float* opW1  = (const float*)d_in[xi + 5];
    const float* opb1  = (const float*)d_in[xi + 6];
    const float* opW2  = (const float*)d_in[xi + 7];
    const float* opb2  = (const float*)d_in[xi + 8];
    const float* opW3  = (const float*)d_in[xi + 9];
    const float* opb3  = (const float*)d_in[xi + 10];
    const float* prW1  = (const float*)d_in[xi + 11];
    const float* prb1  = (const float*)d_in[xi + 12];
    const float* prW2  = (const float*)d_in[xi + 13];
    const float* prb2  = (const float*)d_in[xi + 14];
    const float* prW3  = (const float*)d_in[xi + 15];
    const float* prb3  = (const float*)d_in[xi + 16];
    float* out = (float*)d_out;

    cudaFuncSetAttribute(op_main_kernel,
                         cudaFuncAttributeMaxDynamicSharedMemorySize, SMEM_BYTES);

    precompute_kernel<<<272, 128>>>(y, z, opW1, opb1, prW1, prb1);
    op_main_kernel<<<NBLK, 256, SMEM_BYTES>>>(x, opW2, opb2, opW3, opb3,
                                              opmsk, out);
    finalize_kernel<<<NBLK, 256>>>(out);
    prlvl_kernel<<<NDAG / 4, 256>>>(prW1, prW2, prb2, prW3, prb3, prmsk, out);
}

// round 5
// speedup vs baseline: 1.3843x; 1.3843x over previous
#include <cuda_runtime.h>
#include <cstdint>

#define NOPS  102400
#define NDAG  1024
#define OPD   100
#define EDIM  256
#define H1D   32
#define H2D   16
#define NWRK  64
#define MTILE 256
#define NBLK  (NOPS / MTILE)      // 400

// ---------------- device scratch (no allocations allowed) ----------------
__device__ float  g_Aop[NDAG * H1D];
__device__ float  g_Apr[NDAG * H1D];
__device__ float  g_bmax[NBLK];
__device__ float  g_bsum[NBLK];
__device__ float2 g_Braw[4096];    // [32 kstep][4 nbl][32 lane] = {b0,b1} fp32

// ---------------- smem layout (bytes) ----------------
#define B_OFF   0                  // 32768: B raw fp32 fragments
#define A_OFF   32768              // 2 x 32768: A fragment double buffer (32-k chunks)
#define ABUF    32768
#define W2_OFF  98304              // 512 floats
#define B2_OFF  (W2_OFF + 2048)
#define W3_OFF  (B2_OFF + 64)
#define RED_OFF (W3_OFF + 64)
#define SMEM_BYTES (RED_OFF + 64)  // 100544

// ---------------- helpers ----------------
__device__ __forceinline__ void cp16(uint32_t dst, const void* src) {
    asm volatile("cp.async.cg.shared.global [%0], [%1], 16;" :: "r"(dst), "l"(src));
}
__device__ __forceinline__ void mma_tf32(float* c, const uint32_t* a,
                                         uint32_t b0, uint32_t b1) {
    asm volatile(
        "mma.sync.aligned.m16n8k8.row.col.f32.tf32.tf32.f32 "
        "{%0,%1,%2,%3},{%4,%5,%6,%7},{%8,%9},{%0,%1,%2,%3};"
        : "+f"(c[0]), "+f"(c[1]), "+f"(c[2]), "+f"(c[3])
        : "r"(a[0]), "r"(a[1]), "r"(a[2]), "r"(a[3]), "r"(b0), "r"(b1));
}
__device__ __forceinline__ void split32(float v, uint32_t& hi, uint32_t& lo) {
    uint32_t u = __float_as_uint(v);
    hi = u & 0xFFFFE000u;
    lo = __float_as_uint(v - __uint_as_float(hi));
}

// ---------------------------------------------------------------------------
// pre_dag: per-dag layer-1 partials, 1 block per dag, 4 warps split k
// ---------------------------------------------------------------------------
__global__ __launch_bounds__(128) void pre_dag_kernel(
    const float* __restrict__ y, const float* __restrict__ z,
    const float* __restrict__ opW1, const float* __restrict__ opb1,
    const float* __restrict__ prW1, const float* __restrict__ prb1)
{
    __shared__ float red[2][128];
    const int d = blockIdx.x;
    const int warp = threadIdx.x >> 5;
    const int lane = threadIdx.x & 31;
    const float* yd = y + d * EDIM;
    float aop = 0.f, apr = 0.f;
    const int k0 = warp * 64;
    #pragma unroll 8
    for (int kk = 0; kk < 64; kk++) {
        int k = k0 + kk;
        float yv = __ldg(yd + k);
        float zv = __ldg(z + k);
        aop = fmaf(yv, __ldg(opW1 + (EDIM + k) * H1D + lane), aop);
        aop = fmaf(zv, __ldg(opW1 + (2 * EDIM + k) * H1D + lane), aop);
        apr = fmaf(yv, __ldg(prW1 + (1 + k) * H1D + lane), apr);
        apr = fmaf(zv, __ldg(prW1 + (1 + EDIM + k) * H1D + lane), apr);
    }
    red[0][threadIdx.x] = aop;
    red[1][threadIdx.x] = apr;
    __syncthreads();
    if (warp == 0) {
        float a = red[0][lane] + red[0][32 + lane] + red[0][64 + lane] + red[0][96 + lane];
        float p = red[1][lane] + red[1][32 + lane] + red[1][64 + lane] + red[1][96 + lane];
        g_Aop[d * H1D + lane] = a + opb1[lane];
        g_Apr[d * H1D + lane] = p + prb1[lane];
    }
}

// ---------------------------------------------------------------------------
// pre_B: W1 x-part -> raw fp32 mma fragment order in global
// entry e: lane=e&31, nb=(e>>5)&3, kst=e>>7; b0=W1[kst*8+c][n], b1=W1[kst*8+4+c][n]
// ---------------------------------------------------------------------------
__global__ __launch_bounds__(128) void pre_B_kernel(const float* __restrict__ opW1)
{
    int t = blockIdx.x * 128 + threadIdx.x;
    #pragma unroll
    for (int q = 0; q < 2; q++) {
        int e = t * 2 + q;
        int lane = e & 31;
        int nbl  = (e >> 5) & 3;
        int kst  = e >> 7;
        int k0 = kst * 8 + (lane & 3);
        int n  = nbl * 8 + (lane >> 2);
        float2 v;
        v.x = __ldg(opW1 + k0 * H1D + n);
        v.y = __ldg(opW1 + (k0 + 4) * H1D + n);
        g_Braw[e] = v;
    }
}

// ---------------------------------------------------------------------------
// op main: [256 x 256] x [256 x 32] via 3xTF32 mma.sync, 2 CTAs/SM.
// 8 warps; warp w: rows 32w..32w+31 (2 m-blocks), full N=32 (4 n-blocks).
// A chunks of 32 k, double-buffered, stored raw fp32 in fragment order;
// hi/lo split for A and B done in registers.
// ---------------------------------------------------------------------------
__global__ __launch_bounds__(256, 2) void op_main_kernel(
    const float* __restrict__ x,
    const float* __restrict__ opW2, const float* __restrict__ opb2,
    const float* __restrict__ opW3, const float* __restrict__ opb3,
    const float* __restrict__ opmsk,
    float* __restrict__ out)
{
    extern __shared__ char sm[];
    const float2* s_B = (const float2*)(sm + B_OFF);
    float* s_w2  = (float*)(sm + W2_OFF);
    float* s_b2  = (float*)(sm + B2_OFF);
    float* s_w3  = (float*)(sm + W3_OFF);
    float* s_red = (float*)(sm + RED_OFF);

    const int tid  = threadIdx.x;
    const int warp = tid >> 5;
    const int lane = tid & 31;
    const int g    = lane >> 2;
    const int cc   = lane & 3;
    const int blk  = blockIdx.x;

    // group 0: B raw fragments (32KB, shared -> L2 hits after first CTAs)
    {
        uint32_t db = (uint32_t)__cvta_generic_to_shared(sm + B_OFF);
        #pragma unroll
        for (int i = 0; i < 8; i++) {
            int idx = i * 256 + tid;
            cp16(db + idx * 16, (const char*)g_Braw + idx * 16);
        }
        asm volatile("cp.async.commit_group;");
    }

    // A staging: chunk c = 32 k-values -> fragment layout (8 float4/thread)
    const float4* xs = (const float4*)x + (size_t)(blk * MTILE) * (EDIM / 4);
    auto stageA = [&](int c, int buf) {
        uint32_t ab = (uint32_t)__cvta_generic_to_shared(sm + A_OFF + buf * ABUF);
        #pragma unroll
        for (int i = 0; i < 8; i++) {
            int lin = i * 256 + tid;
            int row = lin >> 3, j = lin & 7;        // j = float4 col within chunk
            int kk = j >> 1, h = j & 1;             // kk: local k8-step 0..3
            int r16 = row & 15, wm = row >> 4;
            int rg = r16 & 7, p = r16 >> 3;
            int s = h * 2 + p;
            int sg = rg ^ ((kk * 2 + h) & 7);
            uint32_t dstf = (uint32_t)((wm * 4 + kk) * 128 + s * 32 + sg * 4);
            cp16(ab + dstf * 4, xs + row * 64 + c * 8 + j);
        }
        asm volatile("cp.async.commit_group;");
    };

    stageA(0, 0);
    stageA(1, 1);

    for (int i = tid; i < H1D * H2D; i += 256) s_w2[i] = opW2[i];
    if (tid < H2D) { s_b2[tid] = opb2[tid]; s_w3[tid] = opW3[tid]; }

    float acc[2][4][4];
    #pragma unroll
    for (int m = 0; m < 2; m++)
        #pragma unroll
        for (int nb = 0; nb < 4; nb++)
            #pragma unroll
            for (int r = 0; r < 4; r++) acc[m][nb][r] = 0.f;

    for (int c = 0; c < 8; c++) {
        if (c < 7) asm volatile("cp.async.wait_group 1;");
        else       asm volatile("cp.async.wait_group 0;");
        __syncthreads();

        const float* ab = (const float*)(sm + A_OFF + (c & 1) * ABUF);
        #pragma unroll
        for (int kk = 0; kk < 4; kk++) {
            const int kstg = c * 4 + kk;
            // B raw: 4 n-blocks, LDS.64 each, split hi/lo in regs
            uint32_t Bh[4][2], Bl[4][2];
            #pragma unroll
            for (int nb = 0; nb < 4; nb++) {
                float2 bv = s_B[(kstg * 4 + nb) * 32 + lane];
                split32(bv.x, Bh[nb][0], Bl[nb][0]);
                split32(bv.y, Bh[nb][1], Bl[nb][1]);
            }
            // A raw: 2 m-blocks x 4 slots, split hi/lo in regs
            uint32_t Ah[2][4], Al[2][4];
            #pragma unroll
            for (int m = 0; m < 2; m++) {
                #pragma unroll
                for (int s = 0; s < 4; s++) {
                    int sg = g ^ ((kk * 2 + (s >> 1)) & 7);
                    float v = ab[((warp * 2 + m) * 4 + kk) * 128 + s * 32 + sg * 4 + cc];
                    split32(v, Ah[m][s], Al[m][s]);
                }
            }
            #pragma unroll
            for (int m = 0; m < 2; m++) {
                #pragma unroll
                for (int nb = 0; nb < 4; nb++) {
                    mma_tf32(acc[m][nb], Ah[m], Bh[nb][0], Bh[nb][1]);
                    mma_tf32(acc[m][nb], Ah[m], Bl[nb][0], Bl[nb][1]);
                    mma_tf32(acc[m][nb], Al[m], Bh[nb][0], Bh[nb][1]);
                }
            }
        }
        __syncthreads();
        if (c < 6) stageA(c + 2, c & 1);
    }

    // ---- scatter C into s_h [256 rows x stride 33] (reuse A buffers) ----
    float* s_h = (float*)(sm + A_OFF);
    #pragma unroll
    for (int m = 0; m < 2; m++) {
        int row = warp * 32 + m * 16 + g;
        #pragma unroll
        for (int nb = 0; nb < 4; nb++) {
            int col = nb * 8 + 2 * cc;
            s_h[row * 33 + col]           = acc[m][nb][0];
            s_h[row * 33 + col + 1]       = acc[m][nb][1];
            s_h[(row + 8) * 33 + col]     = acc[m][nb][2];
            s_h[(row + 8) * 33 + col + 1] = acc[m][nb][3];
        }
    }
    __syncthreads();

    // ---- layers 2/3 + mask: one op per thread ----
    const int gop = blk * MTILE + tid;
    const int dag = gop / OPD;
    const float* A = g_Aop + dag * H1D;
    float h2[H2D];
    #pragma unroll
    for (int j = 0; j < H2D; j++) h2[j] = s_b2[j];
    const float* hrow = s_h + tid * 33;
    #pragma unroll
    for (int k = 0; k < H1D; k++) {
        float hv = fmaxf(hrow[k] + __ldg(A + k), 0.f);
        #pragma unroll
        for (int j = 0; j < H2D; j++) h2[j] = fmaf(hv, s_w2[k * H2D + j], h2[j]);
    }
    float l = __ldg(opb3);
    #pragma unroll
    for (int j = 0; j < H2D; j++) l = fmaf(fmaxf(h2[j], 0.f), s_w3[j], l);
    l -= (1.f - __ldg(opmsk + gop)) * 1000.f;
    out[gop] = l;

    // ---- per-block online softmax partials over 256 logits ----
    float mx = l;
    #pragma unroll
    for (int off = 16; off; off >>= 1)
        mx = fmaxf(mx, __shfl_xor_sync(0xffffffffu, mx, off));
    if (lane == 0) s_red[warp] = mx;
    __syncthreads();
    float bm = s_red[0];
    #pragma unroll
    for (int i = 1; i < 8; i++) bm = fmaxf(bm, s_red[i]);
    float e = __expf(l - bm);
    #pragma unroll
    for (int off = 16; off; off >>= 1)
        e += __shfl_xor_sync(0xffffffffu, e, off);
    if (lane == 0) s_red[8 + warp] = e;
    __syncthreads();
    if (tid == 0) {
        float s = 0.f;
        #pragma unroll
        for (int i = 0; i < 8; i++) s += s_red[8 + i];
        g_bmax[blk] = bm;
        g_bsum[blk] = s;
    }
}

// ---------------------------------------------------------------------------
// finalize: every block redundantly reduces the 400 partials + normalizes
// ---------------------------------------------------------------------------
__global__ __launch_bounds__(256) void finalize_kernel(float* __restrict__ out)
{
    __shared__ float sr[16];
    __shared__ float sM, sS;
    const int tid = threadIdx.x;
    const int wid = tid >> 5, lane = tid & 31;

    float bm0 = g_bmax[tid];
    float bm1 = (tid + 256 < NBLK) ? g_bmax[tid + 256] : -1e30f;
    float m = fmaxf(bm0, bm1);
    #pragma unroll
    for (int off = 16; off; off >>= 1)
        m = fmaxf(m, __shfl_xor_sync(0xffffffffu, m, off));
    if (lane == 0) sr[wid] = m;
    __syncthreads();
    if (tid == 0) {
        float M = sr[0];
        #pragma unroll
        for (int i = 1; i < 8; i++) M = fmaxf(M, sr[i]);
        sM = M;
    }
    __syncthreads();
    const float M = sM;
    float s = g_bsum[tid] * __expf(bm0 - M);
    if (tid + 256 < NBLK) s += g_bsum[tid + 256] * __expf(bm1 - M);
    #pragma unroll
    for (int off = 16; off; off >>= 1)
        s += __shfl_xor_sync(0xffffffffu, s, off);
    if (lane == 0) sr[8 + wid] = s;
    __syncthreads();
    if (tid == 0) {
        float S = 0.f;
        #pragma unroll
        for (int i = 0; i < 8; i++) S += sr[8 + i];
        sS = S;
    }
    __syncthreads();
    const float inv = 1.f / sS;
    const int i = blockIdx.x * 256 + tid;
    out[i] = __expf(out[i] - M) * inv;
}

// ---------------------------------------------------------------------------
// prlvl: 256-thread blocks, 4 dags/block, 64 workers per dag (2 warps)
// ---------------------------------------------------------------------------
__global__ __launch_bounds__(256) void prlvl_kernel(
    const float* __restrict__ prW1,
    const float* __restrict__ prW2, const float* __restrict__ prb2,
    const float* __restrict__ prW3, const float* __restrict__ prb3,
    const float* __restrict__ prmsk,
    float* __restrict__ out)
{
    __shared__ float sA[4 * H1D], sr0[H1D], sw2[H1D * H2D], sb2[H2D], sw3[H2D];
    __shared__ float sp[8], sp2[8];
    const int tid = threadIdx.x;
    const int sub = tid >> 6;
    const int w = tid & 63;
    const int d = blockIdx.x * 4 + sub;

    if (tid < 128) sA[tid] = g_Apr[blockIdx.x * 128 + tid];
    if (tid < H1D) sr0[tid] = prW1[tid];
    for (int i = tid; i < H1D * H2D; i += 256) sw2[i] = prW2[i];
    if (tid < H2D) { sb2[tid] = prb2[tid]; sw3[tid] = prW3[tid]; }
    __syncthreads();

    const float limit = (float)(w + 1);
    const float* A = sA + sub * H1D;
    float h2[H2D];
    #pragma unroll
    for (int j = 0; j < H2D; j++) h2[j] = sb2[j];
    #pragma unroll
    for (int k = 0; k < H1D; k++) {
        float hv = fmaxf(fmaf(limit, sr0[k], A[k]), 0.f);
        #pragma unroll
        for (int j = 0; j < H2D; j++) h2[j] = fmaf(hv, sw2[k * H2D + j], h2[j]);
    }
    float l = __ldg(prb3);
    #pragma unroll
    for (int j = 0; j < H2D; j++) l = fmaf(fmaxf(h2[j], 0.f), sw3[j], l);
    l -= (1.f - __ldg(prmsk + d * NWRK + w)) * 1000.f;

    float m = l;
    #pragma unroll
    for (int off = 16; off; off >>= 1)
        m = fmaxf(m, __shfl_xor_sync(0xffffffffu, m, off));
    if ((tid & 31) == 0) sp[tid >> 5] = m;
    __syncthreads();
    float bm = fmaxf(sp[2 * sub], sp[2 * sub + 1]);
    float eo = __expf(l - bm);
    float e = eo;
    #pragma unroll
    for (int off = 16; off; off >>= 1)
        e += __shfl_xor_sync(0xffffffffu, e, off);
    if ((tid & 31) == 0) sp2[tid >> 5] = e;
    __syncthreads();
    float s = sp2[2 * sub] + sp2[2 * sub + 1];
    out[NOPS + d * NWRK + w] = eo / s;
}

// ---------------------------------------------------------------------------
// Launch. Order matters for profiling: ncu captures the 4th pattern launch,
// so op_main goes 4th. prlvl depends only on pre_dag -> legal before op_main.
// ---------------------------------------------------------------------------
extern "C" void kernel_launch(void* const* d_in, const int* in_sizes, int n_in,
                              void* d_out, int out_size)
{
    const int xi = n_in - 17;
    const float* x     = (const float*)d_in[xi + 0];
    const float* y     = (const float*)d_in[xi + 1];
    const float* z     = (const float*)d_in[xi + 2];
    const float* opmsk = (const float*)d_in[xi + 3];
    const float* prmsk = (const float*)d_in[xi + 4];
    const float* opW1  = (const float*)d_in[xi + 5];
    const float* opb1  = (const float*)d_in[xi + 6];
    const float* opW2  = (const float*)d_in[xi + 7];
    const float* opb2  = (const float*)d_in[xi + 8];
    const float* opW3  = (const float*)d_in[xi + 9];
    const float* opb3  = (const float*)d_in[xi + 10];
    const float* prW1  = (const float*)d_in[xi + 11];
    const float* prb1  = (const float*)d_in[xi + 12];
    const float* prW2  = (const float*)d_in[xi + 13];
    const float* prb2  = (const float*)d_in[xi + 14];
    const float* prW3  = (const float*)d_in[xi + 15];
    const float* prb3  = (const float*)d_in[xi + 16];
    float* out = (float*)d_out;

    cudaFuncSetAttribute(op_main_kernel,
                         cudaFuncAttributeMaxDynamicSharedMemorySize, SMEM_BYTES);

    pre_dag_kernel<<<NDAG, 128>>>(y, z, opW1, opb1, prW1, prb1);
    pre_B_kernel<<<16, 128>>>(opW1);
    prlvl_kernel<<<NDAG / 4, 256>>>(prW1, prW2, prb2, prW3, prb3, prmsk, out);
    op_main_kernel<<<NBLK, 256, SMEM_BYTES>>>(x, opW2, opb2, opW3, opb3,
                                              opmsk, out);
    finalize_kernel<<<NBLK, 256>>>(out);
}

// round 6
// speedup vs baseline: 1.7153x; 1.2391x over previous
#include <cuda_runtime.h>
#include <cstdint>

#define NOPS  102400
#define NDAG  1024
#define OPD   100
#define EDIM  256
#define H1D   32
#define H2D   16
#define NWRK  64
#define MTILE 256
#define NBLK  (NOPS / MTILE)      // 400

// ---------------- device scratch ----------------
__device__ float  g_Aop[NDAG * H1D];
__device__ float  g_bmax[NBLK];
__device__ float  g_bsum[NBLK];
__device__ float2 g_Braw[4096];    // [32 kstep][4 nbl][32 lane] = {b0,b1} fp32

// ---------------- smem layout (bytes) ----------------
// B: 32KB raw fragments. A: 8 warps x (2 bufs x 2KB) = 32KB. misc ~2.2KB.
// Epilogue reuses [0, 33792) as s_h (256 rows x stride 33).
#define B_OFF   0
#define A_OFF   32768
#define AWARP   4096
#define ACHUNK  2048
#define W2_OFF  65536
#define B2_OFF  (W2_OFF + 2048)
#define W3_OFF  (B2_OFF + 64)
#define RED_OFF (W3_OFF + 64)
#define SMEM_BYTES (RED_OFF + 64)   // 67776 -> 3 CTAs/SM

// ---------------- helpers ----------------
__device__ __forceinline__ void cp16(uint32_t dst, const void* src) {
    asm volatile("cp.async.cg.shared.global [%0], [%1], 16;" :: "r"(dst), "l"(src));
}
__device__ __forceinline__ void mma_tf32(float* c, const uint32_t* a,
                                         uint32_t b0, uint32_t b1) {
    asm volatile(
        "mma.sync.aligned.m16n8k8.row.col.f32.tf32.tf32.f32 "
        "{%0,%1,%2,%3},{%4,%5,%6,%7},{%8,%9},{%0,%1,%2,%3};"
        : "+f"(c[0]), "+f"(c[1]), "+f"(c[2]), "+f"(c[3])
        : "r"(a[0]), "r"(a[1]), "r"(a[2]), "r"(a[3]), "r"(b0), "r"(b1));
}
__device__ __forceinline__ void split32(float v, uint32_t& hi, uint32_t& lo) {
    uint32_t u = __float_as_uint(v);
    hi = u & 0xFFFFE000u;
    lo = __float_as_uint(v - __uint_as_float(hi));
}

// ---------------------------------------------------------------------------
// pre_B: W1 x-part -> raw fp32 mma fragment order in global
// ---------------------------------------------------------------------------
__global__ __launch_bounds__(128) void pre_B_kernel(const float* __restrict__ opW1)
{
    int t = blockIdx.x * 128 + threadIdx.x;
    #pragma unroll
    for (int q = 0; q < 2; q++) {
        int e = t * 2 + q;
        int lane = e & 31;
        int nbl  = (e >> 5) & 3;
        int kst  = e >> 7;
        int k0 = kst * 8 + (lane & 3);
        int n  = nbl * 8 + (lane >> 2);
        float2 v;
        v.x = __ldg(opW1 + k0 * H1D + n);
        v.y = __ldg(opW1 + (k0 + 4) * H1D + n);
        g_Braw[e] = v;
    }
}

// ---------------------------------------------------------------------------
// pre_dag_prlvl: one block per dag.
// Phase 1 (128 thr): layer-1 y/z partials for both heads (4-warp k-split).
// Phase 2 (64 thr): full prlvl MLP + per-dag softmax, straight to out.
// ---------------------------------------------------------------------------
__global__ __launch_bounds__(128) void pre_dag_prlvl_kernel(
    const float* __restrict__ y, const float* __restrict__ z,
    const float* __restrict__ opW1, const float* __restrict__ opb1,
    const float* __restrict__ prW1, const float* __restrict__ prb1,
    const float* __restrict__ prW2, const float* __restrict__ prb2,
    const float* __restrict__ prW3, const float* __restrict__ prb3,
    const float* __restrict__ prmsk,
    float* __restrict__ out)
{
    __shared__ float red[2][128];
    __shared__ float sw2[H1D * H2D], sb2[H2D], sw3[H2D], sr0[H1D], sApr[H1D];
    __shared__ float sp[4];
    const int d = blockIdx.x;
    const int tid = threadIdx.x;
    const int warp = tid >> 5;
    const int lane = tid & 31;

    for (int i = tid; i < H1D * H2D; i += 128) sw2[i] = prW2[i];
    if (tid < H2D) { sb2[tid] = prb2[tid]; sw3[tid] = prW3[tid]; }
    if (tid < H1D) sr0[tid] = prW1[tid];   // row 0 of prW1 = limit weights

    const float* yd = y + d * EDIM;
    float aop = 0.f, apr = 0.f;
    const int k0 = warp * 64;
    #pragma unroll 8
    for (int kk = 0; kk < 64; kk++) {
        int k = k0 + kk;
        float yv = __ldg(yd + k);
        float zv = __ldg(z + k);
        aop = fmaf(yv, __ldg(opW1 + (EDIM + k) * H1D + lane), aop);
        aop = fmaf(zv, __ldg(opW1 + (2 * EDIM + k) * H1D + lane), aop);
        apr = fmaf(yv, __ldg(prW1 + (1 + k) * H1D + lane), apr);
        apr = fmaf(zv, __ldg(prW1 + (1 + EDIM + k) * H1D + lane), apr);
    }
    red[0][tid] = aop;
    red[1][tid] = apr;
    __syncthreads();
    if (warp == 0) {
        float a = red[0][lane] + red[0][32 + lane] + red[0][64 + lane] + red[0][96 + lane];
        float p = red[1][lane] + red[1][32 + lane] + red[1][64 + lane] + red[1][96 + lane];
        g_Aop[d * H1D + lane] = a + opb1[lane];
        sApr[lane] = p + prb1[lane];
    }
    __syncthreads();

    // ---- prlvl for this dag: threads 0..63, worker = tid ----
    float l = 0.f, eo = 0.f;
    if (tid < NWRK) {
        const float limit = (float)(tid + 1);
        float h2[H2D];
        #pragma unroll
        for (int j = 0; j < H2D; j++) h2[j] = sb2[j];
        #pragma unroll
        for (int k = 0; k < H1D; k++) {
            float hv = fmaxf(fmaf(limit, sr0[k], sApr[k]), 0.f);
            #pragma unroll
            for (int j = 0; j < H2D; j++) h2[j] = fmaf(hv, sw2[k * H2D + j], h2[j]);
        }
        l = __ldg(prb3);
        #pragma unroll
        for (int j = 0; j < H2D; j++) l = fmaf(fmaxf(h2[j], 0.f), sw3[j], l);
        l -= (1.f - __ldg(prmsk + d * NWRK + tid)) * 1000.f;
        float m = l;
        #pragma unroll
        for (int off = 16; off; off >>= 1)
            m = fmaxf(m, __shfl_xor_sync(0xffffffffu, m, off));
        if (lane == 0) sp[warp] = m;
    }
    __syncthreads();
    if (tid < NWRK) {
        float bm = fmaxf(sp[0], sp[1]);
        eo = __expf(l - bm);
        float e = eo;
        #pragma unroll
        for (int off = 16; off; off >>= 1)
            e += __shfl_xor_sync(0xffffffffu, e, off);
        if (lane == 0) sp[2 + warp] = e;
    }
    __syncthreads();
    if (tid < NWRK)
        out[NOPS + d * NWRK + tid] = eo / (sp[2] + sp[3]);
}

// ---------------------------------------------------------------------------
// op main: [256 x 256] x [256 x 32] via 3xTF32 mma.sync, 3 CTAs/SM.
// Per-warp independent A pipelines (16-k chunks, per-warp double buffer,
// cp.async + __syncwarp only). Warp w owns rows 32w..32w+31.
// ---------------------------------------------------------------------------
__global__ __launch_bounds__(256, 3) void op_main_kernel(
    const float* __restrict__ x,
    const float* __restrict__ opW2, const float* __restrict__ opb2,
    const float* __restrict__ opW3, const float* __restrict__ opb3,
    const float* __restrict__ opmsk,
    float* __restrict__ out)
{
    extern __shared__ char sm[];
    const float2* s_B = (const float2*)(sm + B_OFF);
    float* s_w2  = (float*)(sm + W2_OFF);
    float* s_b2  = (float*)(sm + B2_OFF);
    float* s_w3  = (float*)(sm + W3_OFF);
    float* s_red = (float*)(sm + RED_OFF);

    const int tid  = threadIdx.x;
    const int warp = tid >> 5;
    const int lane = tid & 31;
    const int g    = lane >> 2;
    const int cc   = lane & 3;
    const int blk  = blockIdx.x;

    // group 0: B raw fragments (32KB, block-cooperative)
    {
        uint32_t db = (uint32_t)__cvta_generic_to_shared(sm + B_OFF);
        #pragma unroll
        for (int i = 0; i < 8; i++) {
            int idx = i * 256 + tid;
            cp16(db + idx * 16, (const char*)g_Braw + idx * 16);
        }
        asm volatile("cp.async.commit_group;");
    }

    // per-warp A staging: chunk c = 16 k-values for this warp's 32 rows
    const float4* xs = (const float4*)x + (size_t)(blk * MTILE) * (EDIM / 4);
    const uint32_t awbase = (uint32_t)__cvta_generic_to_shared(sm + A_OFF) + warp * AWARP;
    const int jj = lane & 3;              // float4 col within chunk
    const int kks = jj >> 1, hs = jj & 1; // staging k8-step / half
    auto stageA = [&](int c, int buf) {
        uint32_t ab = awbase + buf * ACHUNK;
        #pragma unroll
        for (int i = 0; i < 4; i++) {
            int r = i * 8 + (lane >> 2);           // local row 0..31
            int p = (r >> 3) & 1, rg = r & 7, wm = r >> 4;
            int s = hs * 2 + p;
            int sg = rg ^ ((kks * 2 + hs) & 7);
            uint32_t dstf = (uint32_t)((wm * 2 + kks) * 128 + s * 32 + sg * 4);
            cp16(ab + dstf * 4, xs + (warp * 32 + r) * 64 + c * 4 + jj);
        }
        asm volatile("cp.async.commit_group;");
    };

    stageA(0, 0);
    stageA(1, 1);

    for (int i = tid; i < H1D * H2D; i += 256) s_w2[i] = opW2[i];
    if (tid < H2D) { s_b2[tid] = opb2[tid]; s_w3[tid] = opW3[tid]; }

    asm volatile("cp.async.wait_group 1;");
    __syncthreads();   // B + own chunk0 visible block/warp-wide

    float acc[2][4][4];
    #pragma unroll
    for (int m = 0; m < 2; m++)
        #pragma unroll
        for (int nb = 0; nb < 4; nb++)
            #pragma unroll
            for (int r = 0; r < 4; r++) acc[m][nb][r] = 0.f;

    for (int c = 0; c < 16; c++) {
        if (c > 0) {
            if (c < 15) asm volatile("cp.async.wait_group 1;");
            else        asm volatile("cp.async.wait_group 0;");
            __syncwarp();
        }
        const float* ab = (const float*)(sm + A_OFF) + warp * (AWARP / 4)
                        + (c & 1) * (ACHUNK / 4);
        #pragma unroll
        for (int kk = 0; kk < 2; kk++) {
            const int kstg = c * 2 + kk;
            uint32_t Ah[2][4], Al[2][4];
            #pragma unroll
            for (int m = 0; m < 2; m++) {
                #pragma unroll
                for (int s = 0; s < 4; s++) {
                    int sg = g ^ ((kk * 2 + (s >> 1)) & 7);
                    float v = ab[(m * 2 + kk) * 128 + s * 32 + sg * 4 + cc];
                    split32(v, Ah[m][s], Al[m][s]);
                }
            }
            #pragma unroll
            for (int nb = 0; nb < 4; nb++) {
                float2 bv = s_B[(kstg * 4 + nb) * 32 + lane];
                uint32_t bh0, bl0, bh1, bl1;
                split32(bv.x, bh0, bl0);
                split32(bv.y, bh1, bl1);
                #pragma unroll
                for (int m = 0; m < 2; m++) {
                    mma_tf32(acc[m][nb], Ah[m], bh0, bh1);
                    mma_tf32(acc[m][nb], Ah[m], bl0, bl1);
                    mma_tf32(acc[m][nb], Al[m], bh0, bh1);
                }
            }
        }
        __syncwarp();
        if (c < 14) stageA(c + 2, c & 1);
    }

    // ---- all warps done with B -> reuse [0, 33792) as s_h stride 33 ----
    __syncthreads();
    float* s_h = (float*)sm;
    #pragma unroll
    for (int m = 0; m < 2; m++) {
        int row = warp * 32 + m * 16 + g;
        #pragma unroll
        for (int nb = 0; nb < 4; nb++) {
            int col = nb * 8 + 2 * cc;
            s_h[row * 33 + col]           = acc[m][nb][0];
            s_h[row * 33 + col + 1]       = acc[m][nb][1];
            s_h[(row + 8) * 33 + col]     = acc[m][nb][2];
            s_h[(row + 8) * 33 + col + 1] = acc[m][nb][3];
        }
    }
    __syncwarp();   // warp w wrote + reads only its own 32 rows

    // ---- layers 2/3 + mask: one op per thread ----
    const int gop = blk * MTILE + tid;
    const int dag = gop / OPD;
    const float* A = g_Aop + dag * H1D;
    float h2[H2D];
    #pragma unroll
    for (int j = 0; j < H2D; j++) h2[j] = s_b2[j];
    const float* hrow = s_h + tid * 33;
    #pragma unroll
    for (int k = 0; k < H1D; k++) {
        float hv = fmaxf(hrow[k] + __ldg(A + k), 0.f);
        #pragma unroll
        for (int j = 0; j < H2D; j++) h2[j] = fmaf(hv, s_w2[k * H2D + j], h2[j]);
    }
    float l = __ldg(opb3);
    #pragma unroll
    for (int j = 0; j < H2D; j++) l = fmaf(fmaxf(h2[j], 0.f), s_w3[j], l);
    l -= (1.f - __ldg(opmsk + gop)) * 1000.f;
    out[gop] = l;

    // ---- per-block online softmax partials over 256 logits ----
    float mx = l;
    #pragma unroll
    for (int off = 16; off; off >>= 1)
        mx = fmaxf(mx, __shfl_xor_sync(0xffffffffu, mx, off));
    if (lane == 0) s_red[warp] = mx;
    __syncthreads();
    float bm = s_red[0];
    #pragma unroll
    for (int i = 1; i < 8; i++) bm = fmaxf(bm, s_red[i]);
    float e = __expf(l - bm);
    #pragma unroll
    for (int off = 16; off; off >>= 1)
        e += __shfl_xor_sync(0xffffffffu, e, off);
    if (lane == 0) s_red[8 + warp] = e;
    __syncthreads();
    if (tid == 0) {
        float s = 0.f;
        #pragma unroll
        for (int i = 0; i < 8; i++) s += s_red[8 + i];
        g_bmax[blk] = bm;
        g_bsum[blk] = s;
    }
}

// ---------------------------------------------------------------------------
// finalize: every block redundantly reduces the 400 partials + normalizes
// ---------------------------------------------------------------------------
__global__ __launch_bounds__(256) void finalize_kernel(float* __restrict__ out)
{
    __shared__ float sr[16];
    __shared__ float sM, sS;
    const int tid = threadIdx.x;
    const int wid = tid >> 5, lane = tid & 31;

    float bm0 = g_bmax[tid];
    float bm1 = (tid + 256 < NBLK) ? g_bmax[tid + 256] : -1e30f;
    float m = fmaxf(bm0, bm1);
    #pragma unroll
    for (int off = 16; off; off >>= 1)
        m = fmaxf(m, __shfl_xor_sync(0xffffffffu, m, off));
    if (lane == 0) sr[wid] = m;
    __syncthreads();
    if (tid == 0) {
        float M = sr[0];
        #pragma unroll
        for (int i = 1; i < 8; i++) M = fmaxf(M, sr[i]);
        sM = M;
    }
    __syncthreads();
    const float M = sM;
    float s = g_bsum[tid] * __expf(bm0 - M);
    if (tid + 256 < NBLK) s += g_bsum[tid + 256] * __expf(bm1 - M);
    #pragma unroll
    for (int off = 16; off; off >>= 1)
        s += __shfl_xor_sync(0xffffffffu, s, off);
    if (lane == 0) sr[8 + wid] = s;
    __syncthreads();
    if (tid == 0) {
        float S = 0.f;
        #pragma unroll
        for (int i = 0; i < 8; i++) S += sr[8 + i];
        sS = S;
    }
    __syncthreads();
    const float inv = 1.f / sS;
    const int i = blockIdx.x * 256 + tid;
    out[i] = __expf(out[i] - M) * inv;
}

// ---------------------------------------------------------------------------
// Launch
// ---------------------------------------------------------------------------
extern "C" void kernel_launch(void* const* d_in, const int* in_sizes, int n_in,
                              void* d_out, int out_size)
{
    const int xi = n_in - 17;
    const float* x     = (const float*)d_in[xi + 0];
    const float* y     = (const float*)d_in[xi + 1];
    const float* z     = (const float*)d_in[xi + 2];
    const float* opmsk = (const float*)d_in[xi + 3];
    const float* prmsk = (const float*)d_in[xi + 4];
    const float* opW1  = (const float*)d_in[xi + 5];
    const float* opb1  = (const float*)d_in[xi + 6];
    const float* opW2  = (const float*)d_in[xi + 7];
    const float* opb2  = (const float*)d_in[xi + 8];
    const float* opW3  = (const float*)d_in[xi + 9];
    const float* opb3  = (const float*)d_in[xi + 10];
    const float* prW1  = (const float*)d_in[xi + 11];
    const float* prb1  = (const float*)d_in[xi + 12];
    const float* prW2  = (const float*)d_in[xi + 13];
    const float* prb2  = (const float*)d_in[xi + 14];
    const float* prW3  = (const float*)d_in[xi + 15];
    const float* prb3  = (const float*)d_in[xi + 16];
    float* out = (float*)d_out;

    cudaFuncSetAttribute(op_main_kernel,
                         cudaFuncAttributeMaxDynamicSharedMemorySize, SMEM_BYTES);

    pre_B_kernel<<<16, 128>>>(opW1);
    pre_dag_prlvl_kernel<<<NDAG, 128>>>(y, z, opW1, opb1, prW1, prb1,
                                        prW2, prb2, prW3, prb3, prmsk, out);
    op_main_kernel<<<NBLK, 256, SMEM_BYTES>>>(x, opW2, opb2, opW3, opb3,
                                              opmsk, out);
    finalize_kernel<<<NBLK, 256>>>(out);
}

// round 7
// speedup vs baseline: 2.3105x; 1.3470x over previous
#include <cuda_runtime.h>
#include <cstdint>

#define NOPS  102400
#define NDAG  1024
#define OPD   100
#define EDIM  256
#define H1D   32
#define H2D   16
#define NWRK  64
#define MTILE 256
#define NBLK  (NOPS / MTILE)      // 400

// ---------------- device scratch ----------------
__device__ float g_Aop[NDAG * H1D];
__device__ float g_bmax[NBLK];
__device__ float g_bsum[NBLK];
__device__ uint4 g_Bfrag[2048];    // [16 kst16][4 nb][32 lane] = {b0hi,b1hi,b0lo,b1lo} bf16x2

// ---------------- smem layout (bytes) ----------------
// B: 32KB packed fragments. A: 8 warps x (2 bufs x 2KB) = 32KB. misc ~2.2KB.
// Epilogue reuses [0, 33792) as s_h (256 rows x stride 33).
#define B_OFF   0
#define A_OFF   32768
#define AWARP   4096
#define ACHUNK  2048
#define W2_OFF  65536
#define B2_OFF  (W2_OFF + 2048)
#define W3_OFF  (B2_OFF + 64)
#define RED_OFF (W3_OFF + 64)
#define SMEM_BYTES (RED_OFF + 64)   // 67776 -> 3 CTAs/SM

// ---------------- helpers ----------------
__device__ __forceinline__ void cp16(uint32_t dst, const void* src) {
    asm volatile("cp.async.cg.shared.global [%0], [%1], 16;" :: "r"(dst), "l"(src));
}
__device__ __forceinline__ void mma_bf16(float* c, const uint32_t* a,
                                         uint32_t b0, uint32_t b1) {
    asm volatile(
        "mma.sync.aligned.m16n8k16.row.col.f32.bf16.bf16.f32 "
        "{%0,%1,%2,%3},{%4,%5,%6,%7},{%8,%9},{%0,%1,%2,%3};"
        : "+f"(c[0]), "+f"(c[1]), "+f"(c[2]), "+f"(c[3])
        : "r"(a[0]), "r"(a[1]), "r"(a[2]), "r"(a[3]), "r"(b0), "r"(b1));
}
// hi = top-16-bit truncation (exact as float), packed bf16x2 {lo-half=elem k}
__device__ __forceinline__ uint32_t pack_hi(float2 v, uint32_t& h0, uint32_t& h1) {
    uint32_t b0 = __float_as_uint(v.x), b1 = __float_as_uint(v.y);
    h0 = b0 & 0xFFFF0000u;
    h1 = b1 & 0xFFFF0000u;
    return __byte_perm(b0, b1, 0x7632);
}
__device__ __forceinline__ uint32_t pack_lo(float2 v, uint32_t h0, uint32_t h1) {
    float l0 = v.x - __uint_as_float(h0);
    float l1 = v.y - __uint_as_float(h1);
    uint32_t r;
    asm("cvt.rn.bf16x2.f32 %0, %1, %2;" : "=r"(r) : "f"(l1), "f"(l0));  // lo-half = l0
    return r;
}

// ---------------------------------------------------------------------------
// pre_dag_prlvl: blocks [0,NDAG): per-dag layer-1 partials (8-warp k-split)
//   then full prlvl MLP + per-dag softmax.
// blocks [NDAG, NDAG+2): B fragment prep (W1 x-part -> packed bf16 hi/lo).
// ---------------------------------------------------------------------------
__global__ __launch_bounds__(256) void pre_kernel(
    const float* __restrict__ y, const float* __restrict__ z,
    const float* __restrict__ opW1, const float* __restrict__ opb1,
    const float* __restrict__ prW1, const float* __restrict__ prb1,
    const float* __restrict__ prW2, const float* __restrict__ prb2,
    const float* __restrict__ prW3, const float* __restrict__ prb3,
    const float* __restrict__ prmsk,
    float* __restrict__ out)
{
    const int tid = threadIdx.x;
    if (blockIdx.x >= NDAG) {
        // ---- B fragments: 2048 uint4 over 2 blocks x 256 thr x 4 ----
        int t = (blockIdx.x - NDAG) * 256 + tid;
        #pragma unroll
        for (int q = 0; q < 4; q++) {
            int e = t * 4 + q;                    // 0..2047
            int lane = e & 31;
            int nb   = (e >> 5) & 3;
            int kst  = e >> 7;                    // 0..15
            int k0 = kst * 16 + 2 * (lane & 3);
            int n  = nb * 8 + (lane >> 2);
            float2 p0 = make_float2(__ldg(opW1 + k0 * H1D + n),
                                    __ldg(opW1 + (k0 + 1) * H1D + n));
            float2 p1 = make_float2(__ldg(opW1 + (k0 + 8) * H1D + n),
                                    __ldg(opW1 + (k0 + 9) * H1D + n));
            uint4 o;
            uint32_t h0, h1, h2, h3;
            o.x = pack_hi(p0, h0, h1);
            o.y = pack_hi(p1, h2, h3);
            o.z = pack_lo(p0, h0, h1);
            o.w = pack_lo(p1, h2, h3);
            g_Bfrag[e] = o;
        }
        return;
    }

    __shared__ float red[2][256];
    __shared__ float sw2[H1D * H2D], sb2[H2D], sw3[H2D], sr0[H1D], sApr[H1D];
    __shared__ float sp[4];
    const int d = blockIdx.x;
    const int warp = tid >> 5;
    const int lane = tid & 31;

    for (int i = tid; i < H1D * H2D; i += 256) sw2[i] = prW2[i];
    if (tid < H2D) { sb2[tid] = prb2[tid]; sw3[tid] = prW3[tid]; }
    if (tid < H1D) sr0[tid] = prW1[tid];   // row 0 of prW1 = limit weights

    const float* yd = y + d * EDIM;
    float aop = 0.f, apr = 0.f;
    const int k0 = warp * 32;
    #pragma unroll 8
    for (int kk = 0; kk < 32; kk++) {
        int k = k0 + kk;
        float yv = __ldg(yd + k);
        float zv = __ldg(z + k);
        aop = fmaf(yv, __ldg(opW1 + (EDIM + k) * H1D + lane), aop);
        aop = fmaf(zv, __ldg(opW1 + (2 * EDIM + k) * H1D + lane), aop);
        apr = fmaf(yv, __ldg(prW1 + (1 + k) * H1D + lane), apr);
        apr = fmaf(zv, __ldg(prW1 + (1 + EDIM + k) * H1D + lane), apr);
    }
    red[0][tid] = aop;
    red[1][tid] = apr;
    __syncthreads();
    if (warp == 0) {
        float a = 0.f, p = 0.f;
        #pragma unroll
        for (int i = 0; i < 8; i++) {
            a += red[0][i * 32 + lane];
            p += red[1][i * 32 + lane];
        }
        g_Aop[d * H1D + lane] = a + opb1[lane];
        sApr[lane] = p + prb1[lane];
    }
    __syncthreads();

    // ---- prlvl for this dag: threads 0..63, worker = tid ----
    float l = 0.f, eo = 0.f;
    if (tid < NWRK) {
        const float limit = (float)(tid + 1);
        float h2[H2D];
        #pragma unroll
        for (int j = 0; j < H2D; j++) h2[j] = sb2[j];
        #pragma unroll
        for (int k = 0; k < H1D; k++) {
            float hv = fmaxf(fmaf(limit, sr0[k], sApr[k]), 0.f);
            #pragma unroll
            for (int j = 0; j < H2D; j++) h2[j] = fmaf(hv, sw2[k * H2D + j], h2[j]);
        }
        l = __ldg(prb3);
        #pragma unroll
        for (int j = 0; j < H2D; j++) l = fmaf(fmaxf(h2[j], 0.f), sw3[j], l);
        l -= (1.f - __ldg(prmsk + d * NWRK + tid)) * 1000.f;
        float m = l;
        #pragma unroll
        for (int off = 16; off; off >>= 1)
            m = fmaxf(m, __shfl_xor_sync(0xffffffffu, m, off));
        if (lane == 0) sp[warp] = m;
    }
    __syncthreads();
    if (tid < NWRK) {
        float bm = fmaxf(sp[0], sp[1]);
        eo = __expf(l - bm);
        float e = eo;
        #pragma unroll
        for (int off = 16; off; off >>= 1)
            e += __shfl_xor_sync(0xffffffffu, e, off);
        if (lane == 0) sp[2 + warp] = e;
    }
    __syncthreads();
    if (tid < NWRK)
        out[NOPS + d * NWRK + tid] = eo / (sp[2] + sp[3]);
}

// ---------------------------------------------------------------------------
// op main: [256 x 256] x [256 x 32] via 3xBF16 mma.sync.m16n8k16, 3 CTAs/SM.
// Per-warp independent A pipelines (16-k chunks = 1 kstep16, double buffer).
// A smem chunk layout: 8 segments (m*2+h)*2+p of 32 float2 (lane' = g*4+cc);
// fragment a0..a3 = (h,p) = (0,0),(0,1),(1,0),(1,1).
// ---------------------------------------------------------------------------
__global__ __launch_bounds__(256, 3) void op_main_kernel(
    const float* __restrict__ x,
    const float* __restrict__ opW2, const float* __restrict__ opb2,
    const float* __restrict__ opW3, const float* __restrict__ opb3,
    const float* __restrict__ opmsk,
    float* __restrict__ out)
{
    extern __shared__ char sm[];
    const uint4* s_B = (const uint4*)(sm + B_OFF);
    float* s_w2  = (float*)(sm + W2_OFF);
    float* s_b2  = (float*)(sm + B2_OFF);
    float* s_w3  = (float*)(sm + W3_OFF);
    float* s_red = (float*)(sm + RED_OFF);

    const int tid  = threadIdx.x;
    const int warp = tid >> 5;
    const int lane = tid & 31;
    const int g    = lane >> 2;
    const int cc   = lane & 3;
    const int blk  = blockIdx.x;

    // group 0: B packed fragments (32KB, block-cooperative)
    {
        uint32_t db = (uint32_t)__cvta_generic_to_shared(sm + B_OFF);
        #pragma unroll
        for (int i = 0; i < 8; i++) {
            int idx = i * 256 + tid;
            cp16(db + idx * 16, (const char*)g_Bfrag + idx * 16);
        }
        asm volatile("cp.async.commit_group;");
    }

    // per-warp A staging: chunk c = one kstep16 for this warp's 32 rows
    const float4* xs = (const float4*)x + (size_t)(blk * MTILE) * (EDIM / 4);
    const uint32_t awbase = (uint32_t)__cvta_generic_to_shared(sm + A_OFF) + warp * AWARP;
    auto stageA = [&](int c, int buf) {
        uint32_t ab = awbase + buf * ACHUNK;
        const int j = lane & 3;                // float4 within row (k 4j..4j+3)
        const int h = j >> 1;
        const int cc0 = (2 * j) & 3;
        #pragma unroll
        for (int i = 0; i < 4; i++) {
            int r = i * 8 + (lane >> 2);       // local row 0..31
            int m = r >> 4, p = (r >> 3) & 1, g2 = r & 7;
            uint32_t dst = (uint32_t)(((m * 2 + h) * 2 + p) * 256 + g2 * 32 + cc0 * 8);
            cp16(ab + dst, xs + (warp * 32 + r) * 64 + c * 4 + j);
        }
        asm volatile("cp.async.commit_group;");
    };

    stageA(0, 0);
    stageA(1, 1);

    for (int i = tid; i < H1D * H2D; i += 256) s_w2[i] = opW2[i];
    if (tid < H2D) { s_b2[tid] = opb2[tid]; s_w3[tid] = opW3[tid]; }

    asm volatile("cp.async.wait_group 1;");
    __syncthreads();   // B + own chunk0 visible

    float acc[2][4][4];
    #pragma unroll
    for (int m = 0; m < 2; m++)
        #pragma unroll
        for (int nb = 0; nb < 4; nb++)
            #pragma unroll
            for (int r = 0; r < 4; r++) acc[m][nb][r] = 0.f;

    const uint32_t aoff = (uint32_t)(g * 32 + cc * 8);

    for (int c = 0; c < 16; c++) {
        if (c > 0) {
            if (c < 15) asm volatile("cp.async.wait_group 1;");
            else        asm volatile("cp.async.wait_group 0;");
            __syncwarp();
        }
        const char* ab = sm + A_OFF + warp * AWARP + (c & 1) * ACHUNK;

        // B fragments for this kstep16: 4 n-blocks
        uint4 Bv[4];
        #pragma unroll
        for (int nb = 0; nb < 4; nb++)
            Bv[nb] = s_B[(c * 4 + nb) * 32 + lane];

        #pragma unroll
        for (int m = 0; m < 2; m++) {
            float2 v0 = *(const float2*)(ab + (m * 4 + 0) * 256 + aoff);  // h0 p0
            float2 v1 = *(const float2*)(ab + (m * 4 + 1) * 256 + aoff);  // h0 p1
            float2 v2 = *(const float2*)(ab + (m * 4 + 2) * 256 + aoff);  // h1 p0
            float2 v3 = *(const float2*)(ab + (m * 4 + 3) * 256 + aoff);  // h1 p1
            uint32_t Ah[4], Al[4];
            uint32_t h0, h1;
            Ah[0] = pack_hi(v0, h0, h1); Al[0] = pack_lo(v0, h0, h1);
            Ah[1] = pack_hi(v1, h0, h1); Al[1] = pack_lo(v1, h0, h1);
            Ah[2] = pack_hi(v2, h0, h1); Al[2] = pack_lo(v2, h0, h1);
            Ah[3] = pack_hi(v3, h0, h1); Al[3] = pack_lo(v3, h0, h1);
            #pragma unroll
            for (int nb = 0; nb < 4; nb++) {
                mma_bf16(acc[m][nb], Ah, Bv[nb].x, Bv[nb].y);
                mma_bf16(acc[m][nb], Ah, Bv[nb].z, Bv[nb].w);
                mma_bf16(acc[m][nb], Al, Bv[nb].x, Bv[nb].y);
            }
        }
        __syncwarp();
        if (c < 14) stageA(c + 2, c & 1);
    }

    // ---- all warps done with B -> reuse [0, 33792) as s_h stride 33 ----
    __syncthreads();
    float* s_h = (float*)sm;
    #pragma unroll
    for (int m = 0; m < 2; m++) {
        int row = warp * 32 + m * 16 + g;
        #pragma unroll
        for (int nb = 0; nb < 4; nb++) {
            int col = nb * 8 + 2 * cc;
            s_h[row * 33 + col]           = acc[m][nb][0];
            s_h[row * 33 + col + 1]       = acc[m][nb][1];
            s_h[(row + 8) * 33 + col]     = acc[m][nb][2];
            s_h[(row + 8) * 33 + col + 1] = acc[m][nb][3];
        }
    }
    __syncwarp();   // warp w wrote + reads only its own 32 rows

    // ---- layers 2/3 + mask: one op per thread ----
    const int gop = blk * MTILE + tid;
    const int dag = gop / OPD;
    const float* A = g_Aop + dag * H1D;
    float h2[H2D];
    #pragma unroll
    for (int j = 0; j < H2D; j++) h2[j] = s_b2[j];
    const float* hrow = s_h + tid * 33;
    #pragma unroll
    for (int k = 0; k < H1D; k++) {
        float hv = fmaxf(hrow[k] + __ldg(A + k), 0.f);
        #pragma unroll
        for (int j = 0; j < H2D; j++) h2[j] = fmaf(hv, s_w2[k * H2D + j], h2[j]);
    }
    float l = __ldg(opb3);
    #pragma unroll
    for (int j = 0; j < H2D; j++) l = fmaf(fmaxf(h2[j], 0.f), s_w3[j], l);
    l -= (1.f - __ldg(opmsk + gop)) * 1000.f;
    out[gop] = l;

    // ---- per-block online softmax partials over 256 logits ----
    float mx = l;
    #pragma unroll
    for (int off = 16; off; off >>= 1)
        mx = fmaxf(mx, __shfl_xor_sync(0xffffffffu, mx, off));
    if (lane == 0) s_red[warp] = mx;
    __syncthreads();
    float bm = s_red[0];
    #pragma unroll
    for (int i = 1; i < 8; i++) bm = fmaxf(bm, s_red[i]);
    float e = __expf(l - bm);
    #pragma unroll
    for (int off = 16; off; off >>= 1)
        e += __shfl_xor_sync(0xffffffffu, e, off);
    if (lane == 0) s_red[8 + warp] = e;
    __syncthreads();
    if (tid == 0) {
        float s = 0.f;
        #pragma unroll
        for (int i = 0; i < 8; i++) s += s_red[8 + i];
        g_bmax[blk] = bm;
        g_bsum[blk] = s;
    }
}

// ---------------------------------------------------------------------------
// finalize: every block redundantly reduces the 400 partials + normalizes
// ---------------------------------------------------------------------------
__global__ __launch_bounds__(256) void finalize_kernel(float* __restrict__ out)
{
    __shared__ float sr[16];
    __shared__ float sM, sS;
    const int tid = threadIdx.x;
    const int wid = tid >> 5, lane = tid & 31;

    float bm0 = g_bmax[tid];
    float bm1 = (tid + 256 < NBLK) ? g_bmax[tid + 256] : -1e30f;
    float m = fmaxf(bm0, bm1);
    #pragma unroll
    for (int off = 16; off; off >>= 1)
        m = fmaxf(m, __shfl_xor_sync(0xffffffffu, m, off));
    if (lane == 0) sr[wid] = m;
    __syncthreads();
    if (tid == 0) {
        float M = sr[0];
        #pragma unroll
        for (int i = 1; i < 8; i++) M = fmaxf(M, sr[i]);
        sM = M;
    }
    __syncthreads();
    const float M = sM;
    float s = g_bsum[tid] * __expf(bm0 - M);
    if (tid + 256 < NBLK) s += g_bsum[tid + 256] * __expf(bm1 - M);
    #pragma unroll
    for (int off = 16; off; off >>= 1)
        s += __shfl_xor_sync(0xffffffffu, s, off);
    if (lane == 0) sr[8 + wid] = s;
    __syncthreads();
    if (tid == 0) {
        float S = 0.f;
        #pragma unroll
        for (int i = 0; i < 8; i++) S += sr[8 + i];
        sS = S;
    }
    __syncthreads();
    const float inv = 1.f / sS;
    const int i = blockIdx.x * 256 + tid;
    out[i] = __expf(out[i] - M) * inv;
}

// ---------------------------------------------------------------------------
// Launch
// ---------------------------------------------------------------------------
extern "C" void kernel_launch(void* const* d_in, const int* in_sizes, int n_in,
                              void* d_out, int out_size)
{
    const int xi = n_in - 17;
    const float* x     = (const float*)d_in[xi + 0];
    const float* y     = (const float*)d_in[xi + 1];
    const float* z     = (const float*)d_in[xi + 2];
    const float* opmsk = (const float*)d_in[xi + 3];
    const float* prmsk = (const float*)d_in[xi + 4];
    const float* opW1  = (const float*)d_in[xi + 5];
    const float* opb1  = (const float*)d_in[xi + 6];
    const float* opW2  = (const float*)d_in[xi + 7];
    const float* opb2  = (const float*)d_in[xi + 8];
    const float* opW3  = (const float*)d_in[xi + 9];
    const float* opb3  = (const float*)d_in[xi + 10];
    const float* prW1  = (const float*)d_in[xi + 11];
    const float* prb1  = (const float*)d_in[xi + 12];
    const float* prW2  = (const float*)d_in[xi + 13];
    const float* prb2  = (const float*)d_in[xi + 14];
    const float* prW3  = (const float*)d_in[xi + 15];
    const float* prb3  = (const float*)d_in[xi + 16];
    float* out = (float*)d_out;

    cudaFuncSetAttribute(op_main_kernel,
                         cudaFuncAttributeMaxDynamicSharedMemorySize, SMEM_BYTES);

    pre_kernel<<<NDAG + 2, 256>>>(y, z, opW1, opb1, prW1, prb1,
                                  prW2, prb2, prW3, prb3, prmsk, out);
    op_main_kernel<<<NBLK, 256, SMEM_BYTES>>>(x, opW2, opb2, opW3, opb3,
                                              opmsk, out);
    finalize_kernel<<<NBLK, 256>>>(out);
}